// round 3
// baseline (speedup 1.0000x reference)
#include <cuda_runtime.h>
#include <cstdint>

#define NB 2
#define NL 1024
#define NCS 384
#define NCZ 128
#define NH 12
#define ND 32
#define NEGV (-10000.0f)

// ---------------- scratch (device globals; allocations are forbidden) -------
__device__ float g_X[NB * NL * NCS];                    // LN output
__device__ float g_Q[NB * NH * NL * ND];                // (b,h,i,d), scale folded
__device__ float g_K[NB * NH * NL * ND];
__device__ float g_V[NB * NH * NL * ND];
__device__ float g_S[(size_t)NB * NL * NH * NL];        // logits (b,i,h,j)  100 MB
__device__ float g_ATT[(size_t)NB * NH * NL * NL];      // attn   (b,h,i,j)  100 MB
__device__ float g_O[NB * NL * NCS];                    // attn@V (b,i,c)

// Mask dtype probe (handles u8 bool / int32 / float32; input is all-ones).
__device__ __forceinline__ bool mask_at(const unsigned char* m, int idx) {
    unsigned int w0 = *(const unsigned int*)m;
    if (w0 == 0x01010101u) return m[idx] != 0;
    if (w0 == 0x3F800000u) return ((const float*)m)[idx] != 0.0f;
    if (w0 == 1u)          return ((const int*)m)[idx] != 0;
    return m[idx] != 0;
}

// ---------------- 1) LayerNorm --------------------------------------------
__global__ void __launch_bounds__(NCS) ln_kernel(const float* __restrict__ s,
                                                 const float* __restrict__ gamma,
                                                 const float* __restrict__ beta) {
    const int row = blockIdx.x;
    const int tid = threadIdx.x;
    __shared__ float red[12];
    float v = s[row * NCS + tid];

    float sum = v;
    #pragma unroll
    for (int o = 16; o > 0; o >>= 1) sum += __shfl_xor_sync(0xffffffffu, sum, o);
    if ((tid & 31) == 0) red[tid >> 5] = sum;
    __syncthreads();
    if (tid < 32) {
        float t = (tid < 12) ? red[tid] : 0.0f;
        #pragma unroll
        for (int o = 16; o > 0; o >>= 1) t += __shfl_xor_sync(0xffffffffu, t, o);
        if (tid == 0) red[0] = t * (1.0f / NCS);
    }
    __syncthreads();
    const float mean = red[0];
    __syncthreads();

    const float d = v - mean;
    float sq = d * d;
    #pragma unroll
    for (int o = 16; o > 0; o >>= 1) sq += __shfl_xor_sync(0xffffffffu, sq, o);
    if ((tid & 31) == 0) red[tid >> 5] = sq;
    __syncthreads();
    if (tid < 32) {
        float t = (tid < 12) ? red[tid] : 0.0f;
        #pragma unroll
        for (int o = 16; o > 0; o >>= 1) t += __shfl_xor_sync(0xffffffffu, t, o);
        if (tid == 0) red[0] = rsqrtf(t * (1.0f / NCS) + 1e-5f);
    }
    __syncthreads();
    const float inv = red[0];
    g_X[row * NCS + tid] = d * inv * gamma[tid] + beta[tid];
}

// ---------------- 2) QKV projection: C[m,n] = dot(X[m,:], W[n,:]) ----------
// 64x64 tile, BK=32, 256 threads, 4x4 register tile. dst laid out (b,h,i,d).
__global__ void __launch_bounds__(256) gemm_qkv_kernel(const float* __restrict__ W,
                                                       const float* __restrict__ bias,
                                                       float scale, int which) {
    __shared__ float As[64][36];
    __shared__ float Bs[32][68];
    float* dst = (which == 0) ? g_Q : (which == 1) ? g_K : g_V;
    const int tid = threadIdx.x;
    const int tx = tid & 15, ty = tid >> 4;
    const int m0 = blockIdx.y * 64, n0 = blockIdx.x * 64;
    float acc[4][4] = {};

    for (int k0 = 0; k0 < NCS; k0 += 32) {
        #pragma unroll
        for (int t = 0; t < 2; t++) {
            int id = tid * 2 + t;
            int r = id >> 3, c4 = (id & 7) * 4;
            *(float4*)&As[r][c4] = *(const float4*)&g_X[(m0 + r) * NCS + k0 + c4];
            float4 vb = *(const float4*)&W[(n0 + r) * NCS + k0 + c4];
            Bs[c4 + 0][r] = vb.x; Bs[c4 + 1][r] = vb.y;
            Bs[c4 + 2][r] = vb.z; Bs[c4 + 3][r] = vb.w;
        }
        __syncthreads();
        #pragma unroll
        for (int k = 0; k < 32; k++) {
            float a0 = As[ty * 4 + 0][k], a1 = As[ty * 4 + 1][k];
            float a2 = As[ty * 4 + 2][k], a3 = As[ty * 4 + 3][k];
            float4 b = *(float4*)&Bs[k][tx * 4];
            acc[0][0] += a0 * b.x; acc[0][1] += a0 * b.y; acc[0][2] += a0 * b.z; acc[0][3] += a0 * b.w;
            acc[1][0] += a1 * b.x; acc[1][1] += a1 * b.y; acc[1][2] += a1 * b.z; acc[1][3] += a1 * b.w;
            acc[2][0] += a2 * b.x; acc[2][1] += a2 * b.y; acc[2][2] += a2 * b.z; acc[2][3] += a2 * b.w;
            acc[3][0] += a3 * b.x; acc[3][1] += a3 * b.y; acc[3][2] += a3 * b.z; acc[3][3] += a3 * b.w;
        }
        __syncthreads();
    }
    #pragma unroll
    for (int i = 0; i < 4; i++) {
        int m = m0 + ty * 4 + i;
        int bb = m >> 10, ii = m & (NL - 1);
        #pragma unroll
        for (int j = 0; j < 4; j++) {
            int n = n0 + tx * 4 + j;
            int h = n >> 5, d = n & 31;
            dst[((bb * NH + h) * NL + ii) * ND + d] = (acc[i][j] + bias[n]) * scale;
        }
    }
}

// ---------------- 3a) S = Q K^T, S layout (b,i,h,j) ------------------------
__global__ void __launch_bounds__(256) gemm_qk_kernel() {
    __shared__ float Qs[64][36];
    __shared__ float Ks[32][68];
    const int tid = threadIdx.x;
    const int tx = tid & 15, ty = tid >> 4;
    const int jt = blockIdx.x, it = blockIdx.y, bh = blockIdx.z;
    const float* Qb = g_Q + ((size_t)bh * NL + it * 64) * ND;
    const float* Kb = g_K + ((size_t)bh * NL + jt * 64) * ND;

    #pragma unroll
    for (int t = 0; t < 2; t++) {
        int id = tid * 2 + t;
        int r = id >> 3, c4 = (id & 7) * 4;
        *(float4*)&Qs[r][c4] = *(const float4*)&Qb[r * ND + c4];
        float4 vk = *(const float4*)&Kb[r * ND + c4];
        Ks[c4 + 0][r] = vk.x; Ks[c4 + 1][r] = vk.y;
        Ks[c4 + 2][r] = vk.z; Ks[c4 + 3][r] = vk.w;
    }
    __syncthreads();
    float acc[4][4] = {};
    #pragma unroll
    for (int k = 0; k < ND; k++) {
        float a0 = Qs[ty * 4 + 0][k], a1 = Qs[ty * 4 + 1][k];
        float a2 = Qs[ty * 4 + 2][k], a3 = Qs[ty * 4 + 3][k];
        float4 b = *(float4*)&Ks[k][tx * 4];
        acc[0][0] += a0 * b.x; acc[0][1] += a0 * b.y; acc[0][2] += a0 * b.z; acc[0][3] += a0 * b.w;
        acc[1][0] += a1 * b.x; acc[1][1] += a1 * b.y; acc[1][2] += a1 * b.z; acc[1][3] += a1 * b.w;
        acc[2][0] += a2 * b.x; acc[2][1] += a2 * b.y; acc[2][2] += a2 * b.z; acc[2][3] += a2 * b.w;
        acc[3][0] += a3 * b.x; acc[3][1] += a3 * b.y; acc[3][2] += a3 * b.z; acc[3][3] += a3 * b.w;
    }
    const int b = bh / NH, h = bh - b * NH;
    #pragma unroll
    for (int i = 0; i < 4; i++) {
        int ii = it * 64 + ty * 4 + i;
        *(float4*)&g_S[((size_t)(b * NL + ii) * NH + h) * NL + jt * 64 + tx * 4] =
            make_float4(acc[i][0], acc[i][1], acc[i][2], acc[i][3]);
    }
}

// ---------------- 3b) fused pair-bias + key-mask + softmax -----------------
// CTA per (b,i). smem: logits[12*1024] + Wp[12*128] + zbuf[256*132] + kok[1024].
#define BS_SMEM ((12 * 1024 + 12 * 128 + 256 * 132 + 1024) * 4)
__global__ void __launch_bounds__(256) bias_softmax_kernel(const float* __restrict__ z,
                                                           const float* __restrict__ Wp,
                                                           const unsigned char* __restrict__ mask) {
    extern __shared__ float sm[];
    float* logits = sm;                        // 12288
    float* wps    = logits + NH * NL;          // 1536
    float* zbuf   = wps + NH * NCZ;            // 256*132
    float* kok    = zbuf + 256 * 132;          // 1024
    const int tid = threadIdx.x;
    const int bi = blockIdx.x;
    const int b = bi >> 10, irow = bi & (NL - 1);

    for (int t = tid; t < NH * NCZ; t += 256) wps[t] = Wp[t];
    for (int t = tid; t < NL; t += 256) kok[t] = mask_at(mask, b * NL + t) ? 1.0f : 0.0f;
    {
        const float4* Srow = (const float4*)&g_S[(size_t)bi * NH * NL];
        float4* l4 = (float4*)logits;
        #pragma unroll
        for (int t = 0; t < 12; t++) l4[t * 256 + tid] = Srow[t * 256 + tid];
    }
    __syncthreads();

    const int jg = tid & 63, hg = tid >> 6;    // tile: 4 j (stride 64) x 3 h
    const float* zrow = z + (size_t)bi * NL * NCZ;

    for (int jb = 0; jb < NL; jb += 256) {
        #pragma unroll 8
        for (int t = 0; t < 32; t++) {         // stage 256x128 z slab (coalesced)
            int id = t * 256 + tid;
            int r = id >> 5, c4 = (id & 31) * 4;
            *(float4*)&zbuf[r * 132 + c4] = *(const float4*)&zrow[(size_t)(jb + r) * NCZ + c4];
        }
        __syncthreads();

        float acc[4][3] = {};
        #pragma unroll 2
        for (int c = 0; c < NCZ; c += 4) {
            float4 z0 = *(float4*)&zbuf[(jg      ) * 132 + c];
            float4 z1 = *(float4*)&zbuf[(jg +  64) * 132 + c];
            float4 z2 = *(float4*)&zbuf[(jg + 128) * 132 + c];
            float4 z3 = *(float4*)&zbuf[(jg + 192) * 132 + c];
            #pragma unroll
            for (int hh = 0; hh < 3; hh++) {
                float4 w = *(float4*)&wps[(hg * 3 + hh) * NCZ + c];
                acc[0][hh] += z0.x * w.x + z0.y * w.y + z0.z * w.z + z0.w * w.w;
                acc[1][hh] += z1.x * w.x + z1.y * w.y + z1.z * w.z + z1.w * w.w;
                acc[2][hh] += z2.x * w.x + z2.y * w.y + z2.z * w.z + z2.w * w.w;
                acc[3][hh] += z3.x * w.x + z3.y * w.y + z3.z * w.z + z3.w * w.w;
            }
        }
        #pragma unroll
        for (int hh = 0; hh < 3; hh++) {
            int h = hg * 3 + hh;
            #pragma unroll
            for (int jj = 0; jj < 4; jj++)
                logits[h * NL + jb + jg + 64 * jj] += acc[jj][hh];
        }
        __syncthreads();
    }

    // softmax: one warp per head (query mask redundant with final *mask)
    const int warp = tid >> 5, lane = tid & 31;
    for (int h = warp; h < NH; h += 8) {
        float* lrow = logits + h * NL;
        float mx = -1e30f;
        for (int t = lane; t < NL; t += 32) {
            float v = (kok[t] != 0.0f) ? lrow[t] : NEGV;
            lrow[t] = v;
            mx = fmaxf(mx, v);
        }
        #pragma unroll
        for (int o = 16; o > 0; o >>= 1) mx = fmaxf(mx, __shfl_xor_sync(0xffffffffu, mx, o));
        float ssum = 0.0f;
        for (int t = lane; t < NL; t += 32) {
            float e = __expf(lrow[t] - mx);
            lrow[t] = e;
            ssum += e;
        }
        #pragma unroll
        for (int o = 16; o > 0; o >>= 1) ssum += __shfl_xor_sync(0xffffffffu, ssum, o);
        const float inv = 1.0f / ssum;
        float* arow = g_ATT + ((size_t)(b * NH + h) * NL + irow) * NL;
        for (int t = lane; t < NL; t += 32) arow[t] = lrow[t] * inv;
    }
}

// ---------------- 4) O = attn @ V  ((b,h,i,j)@(b,h,j,d) -> (b,i,h*32+d)) ---
__global__ void __launch_bounds__(256) gemm_pv_kernel() {
    __shared__ float As[64][36];
    __shared__ float Bs[32][36];
    const int tid = threadIdx.x;
    const int tx = tid & 7, ty = tid >> 3;
    const int it = blockIdx.y, bh = blockIdx.z;
    const int b = bh / NH, h = bh - b * NH;
    const int i0 = it * 64;
    float acc[2][4] = {};

    for (int k0 = 0; k0 < NL; k0 += 32) {
        #pragma unroll
        for (int t = 0; t < 2; t++) {
            int id = tid * 2 + t;
            int r = id >> 3, c4 = (id & 7) * 4;
            *(float4*)&As[r][c4] =
                *(const float4*)&g_ATT[((size_t)bh * NL + i0 + r) * NL + k0 + c4];
        }
        {
            int r = tid >> 3, c4 = (tid & 7) * 4;
            *(float4*)&Bs[r][c4] = *(const float4*)&g_V[((size_t)bh * NL + k0 + r) * ND + c4];
        }
        __syncthreads();
        #pragma unroll
        for (int k = 0; k < 32; k++) {
            float a0 = As[ty * 2 + 0][k], a1 = As[ty * 2 + 1][k];
            float4 v4 = *(float4*)&Bs[k][tx * 4];
            acc[0][0] += a0 * v4.x; acc[0][1] += a0 * v4.y; acc[0][2] += a0 * v4.z; acc[0][3] += a0 * v4.w;
            acc[1][0] += a1 * v4.x; acc[1][1] += a1 * v4.y; acc[1][2] += a1 * v4.z; acc[1][3] += a1 * v4.w;
        }
        __syncthreads();
    }
    #pragma unroll
    for (int i = 0; i < 2; i++) {
        int ii = i0 + ty * 2 + i;
        *(float4*)&g_O[(b * NL + ii) * NCS + h * ND + tx * 4] =
            make_float4(acc[i][0], acc[i][1], acc[i][2], acc[i][3]);
    }
}

// ---------------- 5) out = (O @ Wo^T + bo) * mask --------------------------
__global__ void __launch_bounds__(256) gemm_out_kernel(const float* __restrict__ W,
                                                       const float* __restrict__ bias,
                                                       const unsigned char* __restrict__ mask,
                                                       float* __restrict__ out) {
    __shared__ float As[64][36];
    __shared__ float Bs[32][68];
    const int tid = threadIdx.x;
    const int tx = tid & 15, ty = tid >> 4;
    const int m0 = blockIdx.y * 64, n0 = blockIdx.x * 64;
    float acc[4][4] = {};

    for (int k0 = 0; k0 < NCS; k0 += 32) {
        #pragma unroll
        for (int t = 0; t < 2; t++) {
            int id = tid * 2 + t;
            int r = id >> 3, c4 = (id & 7) * 4;
            *(float4*)&As[r][c4] = *(const float4*)&g_O[(m0 + r) * NCS + k0 + c4];
            float4 vb = *(const float4*)&W[(n0 + r) * NCS + k0 + c4];
            Bs[c4 + 0][r] = vb.x; Bs[c4 + 1][r] = vb.y;
            Bs[c4 + 2][r] = vb.z; Bs[c4 + 3][r] = vb.w;
        }
        __syncthreads();
        #pragma unroll
        for (int k = 0; k < 32; k++) {
            float a0 = As[ty * 4 + 0][k], a1 = As[ty * 4 + 1][k];
            float a2 = As[ty * 4 + 2][k], a3 = As[ty * 4 + 3][k];
            float4 b = *(float4*)&Bs[k][tx * 4];
            acc[0][0] += a0 * b.x; acc[0][1] += a0 * b.y; acc[0][2] += a0 * b.z; acc[0][3] += a0 * b.w;
            acc[1][0] += a1 * b.x; acc[1][1] += a1 * b.y; acc[1][2] += a1 * b.z; acc[1][3] += a1 * b.w;
            acc[2][0] += a2 * b.x; acc[2][1] += a2 * b.y; acc[2][2] += a2 * b.z; acc[2][3] += a2 * b.w;
            acc[3][0] += a3 * b.x; acc[3][1] += a3 * b.y; acc[3][2] += a3 * b.z; acc[3][3] += a3 * b.w;
        }
        __syncthreads();
    }
    #pragma unroll
    for (int i = 0; i < 4; i++) {
        int m = m0 + ty * 4 + i;
        float mk = mask_at(mask, m) ? 1.0f : 0.0f;
        #pragma unroll
        for (int j = 0; j < 4; j++) {
            int n = n0 + tx * 4 + j;
            out[m * NCS + n] = (acc[i][j] + bias[n]) * mk;
        }
    }
}

// ---------------- launcher -------------------------------------------------
extern "C" void kernel_launch(void* const* d_in, const int* in_sizes, int n_in,
                              void* d_out, int out_size) {
    const float* s      = (const float*)d_in[0];
    const float* z      = (const float*)d_in[1];
    const unsigned char* mask = (const unsigned char*)d_in[2];
    const float* Wq     = (const float*)d_in[3];
    const float* bq     = (const float*)d_in[4];
    const float* Wk     = (const float*)d_in[5];
    const float* bk     = (const float*)d_in[6];
    const float* Wv     = (const float*)d_in[7];
    const float* bv     = (const float*)d_in[8];
    const float* Wo     = (const float*)d_in[9];
    const float* bo     = (const float*)d_in[10];
    const float* Wp     = (const float*)d_in[11];
    const float* gamma  = (const float*)d_in[12];
    const float* beta   = (const float*)d_in[13];
    float* out          = (float*)d_out;
    (void)in_sizes; (void)n_in; (void)out_size;

    cudaFuncSetAttribute(bias_softmax_kernel,
                         cudaFuncAttributeMaxDynamicSharedMemorySize, BS_SMEM);

    const float qscale = 0.17677669529663687f;  // 32^-0.5

    ln_kernel<<<NB * NL, NCS>>>(s, gamma, beta);

    dim3 gProj(NCS / 64, (NB * NL) / 64);
    gemm_qkv_kernel<<<gProj, 256>>>(Wq, bq, qscale, 0);
    gemm_qkv_kernel<<<gProj, 256>>>(Wk, bk, 1.0f, 1);
    gemm_qkv_kernel<<<gProj, 256>>>(Wv, bv, 1.0f, 2);

    gemm_qk_kernel<<<dim3(NL / 64, NL / 64, NB * NH), 256>>>();

    bias_softmax_kernel<<<NB * NL, 256, BS_SMEM>>>(z, Wp, mask);

    gemm_pv_kernel<<<dim3(1, NL / 64, NB * NH), 256>>>();

    gemm_out_kernel<<<dim3(NCS / 64, (NB * NL) / 64), 256>>>(Wo, bo, mask, out);
}

// round 5
// speedup vs baseline: 1.2230x; 1.2230x over previous
#include <cuda_runtime.h>
#include <cstdint>

#define NB 2
#define NL 1024
#define NCS 384
#define NCZ 128
#define NH 12
#define ND 32
#define NEGV (-10000.0f)

#define SLABJ 128
#define ZROW 132
#define NSLAB (NL / SLABJ)

// ---------------- scratch (device globals; allocations are forbidden) -------
__device__ float g_X[NB * NL * NCS];
__device__ float g_Q[NB * NH * NL * ND];
__device__ float g_K[NB * NH * NL * ND];
__device__ float g_V[NB * NH * NL * ND];
__device__ float g_S[(size_t)NB * NL * NH * NL];    // logits (b,i,h,j)
__device__ float g_ATT[(size_t)NB * NH * NL * NL];  // attn   (b,h,i,j)
__device__ float g_O[NB * NL * NCS];

__device__ __forceinline__ bool mask_at(const unsigned char* m, int idx) {
    unsigned int w0 = *(const unsigned int*)m;
    if (w0 == 0x01010101u) return m[idx] != 0;
    if (w0 == 0x3F800000u) return ((const float*)m)[idx] != 0.0f;
    if (w0 == 1u)          return ((const int*)m)[idx] != 0;
    return m[idx] != 0;
}

__device__ __forceinline__ void fma2(unsigned long long& d,
                                     unsigned long long a, unsigned long long b) {
    asm("fma.rn.f32x2 %0, %1, %2, %0;" : "+l"(d) : "l"(a), "l"(b));
}

// ---------------- 1) LayerNorm --------------------------------------------
__global__ void __launch_bounds__(NCS) ln_kernel(const float* __restrict__ s,
                                                 const float* __restrict__ gamma,
                                                 const float* __restrict__ beta) {
    const int row = blockIdx.x;
    const int tid = threadIdx.x;
    __shared__ float red[12];
    float v = s[row * NCS + tid];

    float sum = v;
    #pragma unroll
    for (int o = 16; o > 0; o >>= 1) sum += __shfl_xor_sync(0xffffffffu, sum, o);
    if ((tid & 31) == 0) red[tid >> 5] = sum;
    __syncthreads();
    if (tid < 32) {
        float t = (tid < 12) ? red[tid] : 0.0f;
        #pragma unroll
        for (int o = 16; o > 0; o >>= 1) t += __shfl_xor_sync(0xffffffffu, t, o);
        if (tid == 0) red[0] = t * (1.0f / NCS);
    }
    __syncthreads();
    const float mean = red[0];
    __syncthreads();

    const float d = v - mean;
    float sq = d * d;
    #pragma unroll
    for (int o = 16; o > 0; o >>= 1) sq += __shfl_xor_sync(0xffffffffu, sq, o);
    if ((tid & 31) == 0) red[tid >> 5] = sq;
    __syncthreads();
    if (tid < 32) {
        float t = (tid < 12) ? red[tid] : 0.0f;
        #pragma unroll
        for (int o = 16; o > 0; o >>= 1) t += __shfl_xor_sync(0xffffffffu, t, o);
        if (tid == 0) red[0] = rsqrtf(t * (1.0f / NCS) + 1e-5f);
    }
    __syncthreads();
    const float inv = red[0];
    g_X[row * NCS + tid] = d * inv * gamma[tid] + beta[tid];
}

// ---------------- 2) merged QKV projection (grid.z selects Q/K/V) ----------
__global__ void __launch_bounds__(256) gemm_qkv_kernel(const float* __restrict__ Wq,
                                                       const float* __restrict__ bq,
                                                       const float* __restrict__ Wk,
                                                       const float* __restrict__ bk,
                                                       const float* __restrict__ Wv,
                                                       const float* __restrict__ bv) {
    __shared__ float As[64][36];
    __shared__ float Bs[32][68];
    const int which = blockIdx.z;
    const float* W    = (which == 0) ? Wq : (which == 1) ? Wk : Wv;
    const float* bias = (which == 0) ? bq : (which == 1) ? bk : bv;
    float* dst        = (which == 0) ? g_Q : (which == 1) ? g_K : g_V;
    const float scale = (which == 0) ? 0.17677669529663687f : 1.0f;
    const int tid = threadIdx.x;
    const int tx = tid & 15, ty = tid >> 4;
    const int m0 = blockIdx.y * 64, n0 = blockIdx.x * 64;
    float acc[4][4] = {};

    for (int k0 = 0; k0 < NCS; k0 += 32) {
        #pragma unroll
        for (int t = 0; t < 2; t++) {
            int id = tid * 2 + t;
            int r = id >> 3, c4 = (id & 7) * 4;
            *(float4*)&As[r][c4] = *(const float4*)&g_X[(m0 + r) * NCS + k0 + c4];
            float4 vb = *(const float4*)&W[(n0 + r) * NCS + k0 + c4];
            Bs[c4 + 0][r] = vb.x; Bs[c4 + 1][r] = vb.y;
            Bs[c4 + 2][r] = vb.z; Bs[c4 + 3][r] = vb.w;
        }
        __syncthreads();
        #pragma unroll
        for (int k = 0; k < 32; k++) {
            float a0 = As[ty * 4 + 0][k], a1 = As[ty * 4 + 1][k];
            float a2 = As[ty * 4 + 2][k], a3 = As[ty * 4 + 3][k];
            float4 b = *(float4*)&Bs[k][tx * 4];
            acc[0][0] += a0 * b.x; acc[0][1] += a0 * b.y; acc[0][2] += a0 * b.z; acc[0][3] += a0 * b.w;
            acc[1][0] += a1 * b.x; acc[1][1] += a1 * b.y; acc[1][2] += a1 * b.z; acc[1][3] += a1 * b.w;
            acc[2][0] += a2 * b.x; acc[2][1] += a2 * b.y; acc[2][2] += a2 * b.z; acc[2][3] += a2 * b.w;
            acc[3][0] += a3 * b.x; acc[3][1] += a3 * b.y; acc[3][2] += a3 * b.z; acc[3][3] += a3 * b.w;
        }
        __syncthreads();
    }
    #pragma unroll
    for (int i = 0; i < 4; i++) {
        int m = m0 + ty * 4 + i;
        int bb = m >> 10, ii = m & (NL - 1);
        #pragma unroll
        for (int j = 0; j < 4; j++) {
            int n = n0 + tx * 4 + j;
            int h = n >> 5, d = n & 31;
            dst[((bb * NH + h) * NL + ii) * ND + d] = (acc[i][j] + bias[n]) * scale;
        }
    }
}

// ---------------- 3a) S = Q K^T, S layout (b,i,h,j) ------------------------
__global__ void __launch_bounds__(256) gemm_qk_kernel() {
    __shared__ float Qs[64][36];
    __shared__ float Ks[32][68];
    const int tid = threadIdx.x;
    const int tx = tid & 15, ty = tid >> 4;
    const int jt = blockIdx.x, it = blockIdx.y, bh = blockIdx.z;
    const float* Qb = g_Q + ((size_t)bh * NL + it * 64) * ND;
    const float* Kb = g_K + ((size_t)bh * NL + jt * 64) * ND;

    #pragma unroll
    for (int t = 0; t < 2; t++) {
        int id = tid * 2 + t;
        int r = id >> 3, c4 = (id & 7) * 4;
        *(float4*)&Qs[r][c4] = *(const float4*)&Qb[r * ND + c4];
        float4 vk = *(const float4*)&Kb[r * ND + c4];
        Ks[c4 + 0][r] = vk.x; Ks[c4 + 1][r] = vk.y;
        Ks[c4 + 2][r] = vk.z; Ks[c4 + 3][r] = vk.w;
    }
    __syncthreads();
    float acc[4][4] = {};
    #pragma unroll
    for (int k = 0; k < ND; k++) {
        float a0 = Qs[ty * 4 + 0][k], a1 = Qs[ty * 4 + 1][k];
        float a2 = Qs[ty * 4 + 2][k], a3 = Qs[ty * 4 + 3][k];
        float4 b = *(float4*)&Ks[k][tx * 4];
        acc[0][0] += a0 * b.x; acc[0][1] += a0 * b.y; acc[0][2] += a0 * b.z; acc[0][3] += a0 * b.w;
        acc[1][0] += a1 * b.x; acc[1][1] += a1 * b.y; acc[1][2] += a1 * b.z; acc[1][3] += a1 * b.w;
        acc[2][0] += a2 * b.x; acc[2][1] += a2 * b.y; acc[2][2] += a2 * b.z; acc[2][3] += a2 * b.w;
        acc[3][0] += a3 * b.x; acc[3][1] += a3 * b.y; acc[3][2] += a3 * b.z; acc[3][3] += a3 * b.w;
    }
    const int b = bh / NH, h = bh - b * NH;
    #pragma unroll
    for (int i = 0; i < 4; i++) {
        int ii = it * 64 + ty * 4 + i;
        *(float4*)&g_S[((size_t)(b * NL + ii) * NH + h) * NL + jt * 64 + tx * 4] =
            make_float4(acc[i][0], acc[i][1], acc[i][2], acc[i][3]);
    }
}

// ---------------- 3b) fused pair-bias + key-mask + softmax -----------------
// CTA per (b,i). Thread owns 1 j x 12 h x one c-half. f32x2 packed math.
// z double-buffered in 128-j slabs with register prefetch.
#define BS_SMEM ((NH * NL + NH * NCZ + NL + 2 * SLABJ * ZROW) * 4)
__global__ void __launch_bounds__(256) bias_softmax_kernel(const float* __restrict__ z,
                                                           const float* __restrict__ Wp,
                                                           const unsigned char* __restrict__ mask) {
    extern __shared__ float sm[];
    float* logits = sm;                   // 12288
    float* wps    = logits + NH * NL;     // 1536
    float* kok    = wps + NH * NCZ;       // 1024
    float* zbuf   = kok + NL;             // 2 * 128*132
    const int tid = threadIdx.x;
    const int bi  = blockIdx.x;
    const int b = bi >> 10, irow = bi & (NL - 1);

    for (int t = tid; t < NH * NCZ; t += 256) wps[t] = Wp[t];
    for (int t = tid; t < NL; t += 256) kok[t] = mask_at(mask, b * NL + t) ? 1.0f : 0.0f;
    {
        const float4* Srow = (const float4*)&g_S[(size_t)bi * NH * NL];
        float4* l4 = (float4*)logits;
        #pragma unroll
        for (int t = 0; t < 12; t++) l4[t * 256 + tid] = Srow[t * 256 + tid];
    }

    const float* zrow = z + (size_t)bi * NL * NCZ;
    {   // stage slab 0
        const float4* src = (const float4*)zrow;
        #pragma unroll
        for (int k = 0; k < 16; k++) {
            int f = tid + k * 256;
            *(float4*)&zbuf[(f >> 5) * ZROW + (f & 31) * 4] = src[f];
        }
    }
    __syncthreads();

    const int jg = tid & 127;          // j within slab
    const int cg = tid >> 7;           // c-half
    const int cbase = cg * 64;

    for (int sb = 0; sb < NSLAB; sb++) {
        float* zb = zbuf + (sb & 1) * (SLABJ * ZROW);
        float4 pf[16];
        if (sb + 1 < NSLAB) {          // prefetch next slab into registers
            const float4* src = (const float4*)(zrow + (size_t)(sb + 1) * SLABJ * NCZ);
            #pragma unroll
            for (int k = 0; k < 16; k++) pf[k] = src[tid + k * 256];
        }

        unsigned long long acc[NH];
        #pragma unroll
        for (int h = 0; h < NH; h++) acc[h] = 0ULL;
        const float* zr = zb + jg * ZROW + cbase;
        #pragma unroll 4
        for (int c = 0; c < 64; c += 4) {
            ulonglong2 z2 = *(const ulonglong2*)(zr + c);
            #pragma unroll
            for (int h = 0; h < NH; h++) {
                ulonglong2 w2 = *(const ulonglong2*)&wps[h * NCZ + cbase + c];
                fma2(acc[h], z2.x, w2.x);
                fma2(acc[h], z2.y, w2.y);
            }
        }

        const int jj = sb * SLABJ + jg;
        if (cg == 0) {
            #pragma unroll
            for (int h = 0; h < NH; h++) {
                float lo = __int_as_float((int)(acc[h] & 0xffffffffULL));
                float hi = __int_as_float((int)(acc[h] >> 32));
                logits[h * NL + jj] += lo + hi;
            }
        }
        __syncthreads();
        if (cg == 1) {
            #pragma unroll
            for (int h = 0; h < NH; h++) {
                float lo = __int_as_float((int)(acc[h] & 0xffffffffULL));
                float hi = __int_as_float((int)(acc[h] >> 32));
                logits[h * NL + jj] += lo + hi;
            }
        }
        if (sb + 1 < NSLAB) {          // commit prefetched slab to other buffer
            float* nb = zbuf + ((sb + 1) & 1) * (SLABJ * ZROW);
            #pragma unroll
            for (int k = 0; k < 16; k++) {
                int f = tid + k * 256;
                *(float4*)&nb[(f >> 5) * ZROW + (f & 31) * 4] = pf[k];
            }
        }
        __syncthreads();
    }

    // softmax: one warp per head (query mask redundant with final *mask)
    const int warp = tid >> 5, lane = tid & 31;
    for (int h = warp; h < NH; h += 8) {
        float* lrow = logits + h * NL;
        float mx = -1e30f;
        for (int t = lane; t < NL; t += 32) {
            float v = (kok[t] != 0.0f) ? lrow[t] : NEGV;
            lrow[t] = v;
            mx = fmaxf(mx, v);
        }
        #pragma unroll
        for (int o = 16; o > 0; o >>= 1) mx = fmaxf(mx, __shfl_xor_sync(0xffffffffu, mx, o));
        float ssum = 0.0f;
        for (int t = lane; t < NL; t += 32) {
            float e = __expf(lrow[t] - mx);
            lrow[t] = e;
            ssum += e;
        }
        #pragma unroll
        for (int o = 16; o > 0; o >>= 1) ssum += __shfl_xor_sync(0xffffffffu, ssum, o);
        const float inv = 1.0f / ssum;
        float* arow = g_ATT + ((size_t)(b * NH + h) * NL + irow) * NL;
        for (int t = lane; t < NL; t += 32) arow[t] = lrow[t] * inv;
    }
}

// ---------------- 4) O = attn @ V (64i x 32d tiles, BK=64) -----------------
__global__ void __launch_bounds__(256) gemm_pv_kernel() {
    __shared__ float As[64][68];
    __shared__ float Bs[64][36];
    const int tid = threadIdx.x;
    const int tx = tid & 7, ty = tid >> 3;     // ty 0..31 -> 2 i rows each
    const int it = blockIdx.x, bh = blockIdx.y;
    const int b = bh / NH, h = bh - b * NH;
    const int i0 = it * 64;
    float acc[2][4] = {};

    for (int k0 = 0; k0 < NL; k0 += 64) {
        #pragma unroll
        for (int t = 0; t < 4; t++) {
            int id = tid + t * 256;
            int r = id >> 4, c4 = (id & 15) * 4;
            *(float4*)&As[r][c4] =
                *(const float4*)&g_ATT[((size_t)bh * NL + i0 + r) * NL + k0 + c4];
        }
        #pragma unroll
        for (int t = 0; t < 2; t++) {
            int id = tid + t * 256;
            int r = id >> 3, c4 = (id & 7) * 4;
            *(float4*)&Bs[r][c4] = *(const float4*)&g_V[((size_t)bh * NL + k0 + r) * ND + c4];
        }
        __syncthreads();
        #pragma unroll
        for (int k = 0; k < 64; k++) {
            float a0 = As[ty * 2 + 0][k], a1 = As[ty * 2 + 1][k];
            float4 v4 = *(float4*)&Bs[k][tx * 4];
            acc[0][0] += a0 * v4.x; acc[0][1] += a0 * v4.y; acc[0][2] += a0 * v4.z; acc[0][3] += a0 * v4.w;
            acc[1][0] += a1 * v4.x; acc[1][1] += a1 * v4.y; acc[1][2] += a1 * v4.z; acc[1][3] += a1 * v4.w;
        }
        __syncthreads();
    }
    #pragma unroll
    for (int i = 0; i < 2; i++) {
        int ii = i0 + ty * 2 + i;
        *(float4*)&g_O[(b * NL + ii) * NCS + h * ND + tx * 4] =
            make_float4(acc[i][0], acc[i][1], acc[i][2], acc[i][3]);
    }
}

// ---------------- 5) out = (O @ Wo^T + bo) * mask --------------------------
__global__ void __launch_bounds__(256) gemm_out_kernel(const float* __restrict__ W,
                                                       const float* __restrict__ bias,
                                                       const unsigned char* __restrict__ mask,
                                                       float* __restrict__ out) {
    __shared__ float As[64][36];
    __shared__ float Bs[32][68];
    const int tid = threadIdx.x;
    const int tx = tid & 15, ty = tid >> 4;
    const int m0 = blockIdx.y * 64, n0 = blockIdx.x * 64;
    float acc[4][4] = {};

    for (int k0 = 0; k0 < NCS; k0 += 32) {
        #pragma unroll
        for (int t = 0; t < 2; t++) {
            int id = tid * 2 + t;
            int r = id >> 3, c4 = (id & 7) * 4;
            *(float4*)&As[r][c4] = *(const float4*)&g_O[(m0 + r) * NCS + k0 + c4];
            float4 vb = *(const float4*)&W[(n0 + r) * NCS + k0 + c4];
            Bs[c4 + 0][r] = vb.x; Bs[c4 + 1][r] = vb.y;
            Bs[c4 + 2][r] = vb.z; Bs[c4 + 3][r] = vb.w;
        }
        __syncthreads();
        #pragma unroll
        for (int k = 0; k < 32; k++) {
            float a0 = As[ty * 4 + 0][k], a1 = As[ty * 4 + 1][k];
            float a2 = As[ty * 4 + 2][k], a3 = As[ty * 4 + 3][k];
            float4 b = *(float4*)&Bs[k][tx * 4];
            acc[0][0] += a0 * b.x; acc[0][1] += a0 * b.y; acc[0][2] += a0 * b.z; acc[0][3] += a0 * b.w;
            acc[1][0] += a1 * b.x; acc[1][1] += a1 * b.y; acc[1][2] += a1 * b.z; acc[1][3] += a1 * b.w;
            acc[2][0] += a2 * b.x; acc[2][1] += a2 * b.y; acc[2][2] += a2 * b.z; acc[2][3] += a2 * b.w;
            acc[3][0] += a3 * b.x; acc[3][1] += a3 * b.y; acc[3][2] += a3 * b.z; acc[3][3] += a3 * b.w;
        }
        __syncthreads();
    }
    #pragma unroll
    for (int i = 0; i < 4; i++) {
        int m = m0 + ty * 4 + i;
        float mk = mask_at(mask, m) ? 1.0f : 0.0f;
        #pragma unroll
        for (int j = 0; j < 4; j++) {
            int n = n0 + tx * 4 + j;
            out[m * NCS + n] = (acc[i][j] + bias[n]) * mk;
        }
    }
}

// ---------------- launcher -------------------------------------------------
extern "C" void kernel_launch(void* const* d_in, const int* in_sizes, int n_in,
                              void* d_out, int out_size) {
    const float* s      = (const float*)d_in[0];
    const float* z      = (const float*)d_in[1];
    const unsigned char* mask = (const unsigned char*)d_in[2];
    const float* Wq     = (const float*)d_in[3];
    const float* bq     = (const float*)d_in[4];
    const float* Wk     = (const float*)d_in[5];
    const float* bk     = (const float*)d_in[6];
    const float* Wv     = (const float*)d_in[7];
    const float* bv     = (const float*)d_in[8];
    const float* Wo     = (const float*)d_in[9];
    const float* bo     = (const float*)d_in[10];
    const float* Wp     = (const float*)d_in[11];
    const float* gamma  = (const float*)d_in[12];
    const float* beta   = (const float*)d_in[13];
    float* out          = (float*)d_out;
    (void)in_sizes; (void)n_in; (void)out_size;

    cudaFuncSetAttribute(bias_softmax_kernel,
                         cudaFuncAttributeMaxDynamicSharedMemorySize, BS_SMEM);

    ln_kernel<<<NB * NL, NCS>>>(s, gamma, beta);

    gemm_qkv_kernel<<<dim3(NCS / 64, (NB * NL) / 64, 3), 256>>>(Wq, bq, Wk, bk, Wv, bv);

    gemm_qk_kernel<<<dim3(NL / 64, NL / 64, NB * NH), 256>>>();

    bias_softmax_kernel<<<NB * NL, 256, BS_SMEM>>>(z, Wp, mask);

    gemm_pv_kernel<<<dim3(NL / 64, NB * NH), 256>>>();

    gemm_out_kernel<<<dim3(NCS / 64, (NB * NL) / 64), 256>>>(Wo, bo, mask, out);
}

// round 6
// speedup vs baseline: 1.4835x; 1.2130x over previous
#include <cuda_runtime.h>
#include <cstdint>

#define NB 2
#define NL 1024
#define NCS 384
#define NCZ 128
#define NH 12
#define ND 32
#define NEGV (-10000.0f)

// bias kernel staging: slab = 1024 j x 16 c, double buffered
#define CSLAB 16
#define NCSLAB (NCZ / CSLAB)   // 8
#define ZPITCH 20              // 16 + 4 pad (floats); 80B row, float4-aligned

// ---------------- scratch (device globals; allocations are forbidden) -------
__device__ float g_X[NB * NL * NCS];
__device__ float g_Q[NB * NH * NL * ND];
__device__ float g_K[NB * NH * NL * ND];
__device__ float g_V[NB * NH * NL * ND];
__device__ float g_S[(size_t)NB * NL * NH * NL];    // logits (b,i,h,j)
__device__ float g_ATT[(size_t)NB * NH * NL * NL];  // attn   (b,h,i,j)
__device__ float g_O[NB * NL * NCS];

__device__ __forceinline__ bool mask_at(const unsigned char* m, int idx) {
    unsigned int w0 = *(const unsigned int*)m;
    if (w0 == 0x01010101u) return m[idx] != 0;
    if (w0 == 0x3F800000u) return ((const float*)m)[idx] != 0.0f;
    if (w0 == 1u)          return ((const int*)m)[idx] != 0;
    return m[idx] != 0;
}

__device__ __forceinline__ void fma2(unsigned long long& d,
                                     unsigned long long a, unsigned long long b) {
    asm("fma.rn.f32x2 %0, %1, %2, %0;" : "+l"(d) : "l"(a), "l"(b));
}

__device__ __forceinline__ void cp_async16(void* smem_dst, const void* gmem_src) {
    unsigned sa = (unsigned)__cvta_generic_to_shared(smem_dst);
    asm volatile("cp.async.cg.shared.global [%0], [%1], 16;" :: "r"(sa), "l"(gmem_src));
}
__device__ __forceinline__ void cp_commit() {
    asm volatile("cp.async.commit_group;");
}
template <int N>
__device__ __forceinline__ void cp_wait() {
    asm volatile("cp.async.wait_group %0;" :: "n"(N));
}

// ---------------- 1) LayerNorm --------------------------------------------
__global__ void __launch_bounds__(NCS) ln_kernel(const float* __restrict__ s,
                                                 const float* __restrict__ gamma,
                                                 const float* __restrict__ beta) {
    const int row = blockIdx.x;
    const int tid = threadIdx.x;
    __shared__ float red[12];
    float v = s[row * NCS + tid];

    float sum = v;
    #pragma unroll
    for (int o = 16; o > 0; o >>= 1) sum += __shfl_xor_sync(0xffffffffu, sum, o);
    if ((tid & 31) == 0) red[tid >> 5] = sum;
    __syncthreads();
    if (tid < 32) {
        float t = (tid < 12) ? red[tid] : 0.0f;
        #pragma unroll
        for (int o = 16; o > 0; o >>= 1) t += __shfl_xor_sync(0xffffffffu, t, o);
        if (tid == 0) red[0] = t * (1.0f / NCS);
    }
    __syncthreads();
    const float mean = red[0];
    __syncthreads();

    const float d = v - mean;
    float sq = d * d;
    #pragma unroll
    for (int o = 16; o > 0; o >>= 1) sq += __shfl_xor_sync(0xffffffffu, sq, o);
    if ((tid & 31) == 0) red[tid >> 5] = sq;
    __syncthreads();
    if (tid < 32) {
        float t = (tid < 12) ? red[tid] : 0.0f;
        #pragma unroll
        for (int o = 16; o > 0; o >>= 1) t += __shfl_xor_sync(0xffffffffu, t, o);
        if (tid == 0) red[0] = rsqrtf(t * (1.0f / NCS) + 1e-5f);
    }
    __syncthreads();
    const float inv = red[0];
    g_X[row * NCS + tid] = d * inv * gamma[tid] + beta[tid];
}

// ---------------- 2) merged QKV projection (grid.z selects Q/K/V) ----------
__global__ void __launch_bounds__(256) gemm_qkv_kernel(const float* __restrict__ Wq,
                                                       const float* __restrict__ bq,
                                                       const float* __restrict__ Wk,
                                                       const float* __restrict__ bk,
                                                       const float* __restrict__ Wv,
                                                       const float* __restrict__ bv) {
    __shared__ float As[64][36];
    __shared__ float Bs[32][68];
    const int which = blockIdx.z;
    const float* W    = (which == 0) ? Wq : (which == 1) ? Wk : Wv;
    const float* bias = (which == 0) ? bq : (which == 1) ? bk : bv;
    float* dst        = (which == 0) ? g_Q : (which == 1) ? g_K : g_V;
    const float scale = (which == 0) ? 0.17677669529663687f : 1.0f;
    const int tid = threadIdx.x;
    const int tx = tid & 15, ty = tid >> 4;
    const int m0 = blockIdx.y * 64, n0 = blockIdx.x * 64;
    float acc[4][4] = {};

    for (int k0 = 0; k0 < NCS; k0 += 32) {
        #pragma unroll
        for (int t = 0; t < 2; t++) {
            int id = tid * 2 + t;
            int r = id >> 3, c4 = (id & 7) * 4;
            *(float4*)&As[r][c4] = *(const float4*)&g_X[(m0 + r) * NCS + k0 + c4];
            float4 vb = *(const float4*)&W[(n0 + r) * NCS + k0 + c4];
            Bs[c4 + 0][r] = vb.x; Bs[c4 + 1][r] = vb.y;
            Bs[c4 + 2][r] = vb.z; Bs[c4 + 3][r] = vb.w;
        }
        __syncthreads();
        #pragma unroll
        for (int k = 0; k < 32; k++) {
            float a0 = As[ty * 4 + 0][k], a1 = As[ty * 4 + 1][k];
            float a2 = As[ty * 4 + 2][k], a3 = As[ty * 4 + 3][k];
            float4 b = *(float4*)&Bs[k][tx * 4];
            acc[0][0] += a0 * b.x; acc[0][1] += a0 * b.y; acc[0][2] += a0 * b.z; acc[0][3] += a0 * b.w;
            acc[1][0] += a1 * b.x; acc[1][1] += a1 * b.y; acc[1][2] += a1 * b.z; acc[1][3] += a1 * b.w;
            acc[2][0] += a2 * b.x; acc[2][1] += a2 * b.y; acc[2][2] += a2 * b.z; acc[2][3] += a2 * b.w;
            acc[3][0] += a3 * b.x; acc[3][1] += a3 * b.y; acc[3][2] += a3 * b.z; acc[3][3] += a3 * b.w;
        }
        __syncthreads();
    }
    #pragma unroll
    for (int i = 0; i < 4; i++) {
        int m = m0 + ty * 4 + i;
        int bb = m >> 10, ii = m & (NL - 1);
        #pragma unroll
        for (int j = 0; j < 4; j++) {
            int n = n0 + tx * 4 + j;
            int h = n >> 5, d = n & 31;
            dst[((bb * NH + h) * NL + ii) * ND + d] = (acc[i][j] + bias[n]) * scale;
        }
    }
}

// ---------------- 3a) S = Q K^T, S layout (b,i,h,j) ------------------------
__global__ void __launch_bounds__(256) gemm_qk_kernel() {
    __shared__ float Qs[64][36];
    __shared__ float Ks[32][68];
    const int tid = threadIdx.x;
    const int tx = tid & 15, ty = tid >> 4;
    const int jt = blockIdx.x, it = blockIdx.y, bh = blockIdx.z;
    const float* Qb = g_Q + ((size_t)bh * NL + it * 64) * ND;
    const float* Kb = g_K + ((size_t)bh * NL + jt * 64) * ND;

    #pragma unroll
    for (int t = 0; t < 2; t++) {
        int id = tid * 2 + t;
        int r = id >> 3, c4 = (id & 7) * 4;
        *(float4*)&Qs[r][c4] = *(const float4*)&Qb[r * ND + c4];
        float4 vk = *(const float4*)&Kb[r * ND + c4];
        Ks[c4 + 0][r] = vk.x; Ks[c4 + 1][r] = vk.y;
        Ks[c4 + 2][r] = vk.z; Ks[c4 + 3][r] = vk.w;
    }
    __syncthreads();
    float acc[4][4] = {};
    #pragma unroll
    for (int k = 0; k < ND; k++) {
        float a0 = Qs[ty * 4 + 0][k], a1 = Qs[ty * 4 + 1][k];
        float a2 = Qs[ty * 4 + 2][k], a3 = Qs[ty * 4 + 3][k];
        float4 b = *(float4*)&Ks[k][tx * 4];
        acc[0][0] += a0 * b.x; acc[0][1] += a0 * b.y; acc[0][2] += a0 * b.z; acc[0][3] += a0 * b.w;
        acc[1][0] += a1 * b.x; acc[1][1] += a1 * b.y; acc[1][2] += a1 * b.z; acc[1][3] += a1 * b.w;
        acc[2][0] += a2 * b.x; acc[2][1] += a2 * b.y; acc[2][2] += a2 * b.z; acc[2][3] += a2 * b.w;
        acc[3][0] += a3 * b.x; acc[3][1] += a3 * b.y; acc[3][2] += a3 * b.z; acc[3][3] += a3 * b.w;
    }
    const int b = bh / NH, h = bh - b * NH;
    #pragma unroll
    for (int i = 0; i < 4; i++) {
        int ii = it * 64 + ty * 4 + i;
        *(float4*)&g_S[((size_t)(b * NL + ii) * NH + h) * NL + jt * 64 + tx * 4] =
            make_float4(acc[i][0], acc[i][1], acc[i][2], acc[i][3]);
    }
}

// ---------------- 3b) fused pair-bias + key-mask + softmax -----------------
// CTA per (b,i), 512 threads. Thread tile: 4 j x 6 h, f32x2 packed math.
// z staged as c-chunk slabs (1024 j x 16 c = 64KB) double-buffered via cp.async.
#define BS_SMEM ((NH * NL + NH * NCZ + NL + 2 * NL * ZPITCH) * 4)
__global__ void __launch_bounds__(512) bias_softmax_kernel(const float* __restrict__ z,
                                                           const float* __restrict__ Wp,
                                                           const unsigned char* __restrict__ mask) {
    extern __shared__ float sm[];
    float* logits = sm;                   // 12288
    float* wps    = logits + NH * NL;     // 1536
    float* kok    = wps + NH * NCZ;       // 1024
    float* zbuf   = kok + NL;             // 2 * 1024*20
    const int tid  = threadIdx.x;
    const int bi   = blockIdx.x;
    const int b = bi >> 10, irow = bi & (NL - 1);

    for (int t = tid; t < NH * NCZ; t += 512) wps[t] = Wp[t];
    for (int t = tid; t < NL; t += 512) kok[t] = mask_at(mask, b * NL + t) ? 1.0f : 0.0f;
    {
        const float4* Srow = (const float4*)&g_S[(size_t)bi * NH * NL];
        float4* l4 = (float4*)logits;
        #pragma unroll
        for (int t = 0; t < 6; t++) l4[t * 512 + tid] = Srow[t * 512 + tid];
    }

    const float* zrow = z + (size_t)bi * NL * NCZ;

    // stage slab s into buffer (s&1): per thread 8 x cp.async16
    auto stage = [&](int s) {
        float* buf = zbuf + (s & 1) * (NL * ZPITCH);
        #pragma unroll
        for (int k = 0; k < 8; k++) {
            int f  = tid + k * 512;          // 0..4095 float4 slots
            int j  = f >> 2;
            int c4 = (f & 3) * 4;
            cp_async16(&buf[j * ZPITCH + c4], &zrow[(size_t)j * NCZ + s * CSLAB + c4]);
        }
        cp_commit();
    };

    stage(0);

    // thread tiling: warp w(0..15): hg = w>>3 (h base hg*6), jw = w&7; lane l.
    // j's: jb = jw*128 + l, + {0,32,64,96}
    const int lane = tid & 31, warp = tid >> 5;
    const int hg = warp >> 3;
    const int jb = (warp & 7) * 128 + lane;
    const float* wbase = wps + hg * 6 * NCZ;

    unsigned long long acc2[4][6];
    #pragma unroll
    for (int k = 0; k < 4; k++)
        #pragma unroll
        for (int hh = 0; hh < 6; hh++) acc2[k][hh] = 0ULL;

    for (int s = 0; s < NCSLAB; s++) {
        if (s + 1 < NCSLAB) { stage(s + 1); cp_wait<1>(); }
        else                { cp_wait<0>(); }
        __syncthreads();

        const float* buf = zbuf + (s & 1) * (NL * ZPITCH);
        #pragma unroll
        for (int cq = 0; cq < CSLAB; cq += 4) {
            ulonglong2 zq[4];
            #pragma unroll
            for (int k = 0; k < 4; k++)
                zq[k] = *(const ulonglong2*)&buf[(jb + k * 32) * ZPITCH + cq];
            #pragma unroll
            for (int hh = 0; hh < 6; hh++) {
                ulonglong2 wq = *(const ulonglong2*)&wbase[hh * NCZ + s * CSLAB + cq];
                #pragma unroll
                for (int k = 0; k < 4; k++) {
                    fma2(acc2[k][hh], zq[k].x, wq.x);
                    fma2(acc2[k][hh], zq[k].y, wq.y);
                }
            }
        }
        __syncthreads();
    }

    // merge into logits: each (h,j) owned by exactly one thread
    #pragma unroll
    for (int hh = 0; hh < 6; hh++) {
        int h = hg * 6 + hh;
        #pragma unroll
        for (int k = 0; k < 4; k++) {
            float lo = __int_as_float((int)(acc2[k][hh] & 0xffffffffULL));
            float hi = __int_as_float((int)(acc2[k][hh] >> 32));
            logits[h * NL + jb + k * 32] += lo + hi;
        }
    }
    __syncthreads();

    // softmax: one warp per head (query mask redundant with final *mask)
    if (warp < NH) {
        const int h = warp;
        float* lrow = logits + h * NL;
        float mx = -1e30f;
        for (int t = lane; t < NL; t += 32) {
            float v = (kok[t] != 0.0f) ? lrow[t] : NEGV;
            lrow[t] = v;
            mx = fmaxf(mx, v);
        }
        #pragma unroll
        for (int o = 16; o > 0; o >>= 1) mx = fmaxf(mx, __shfl_xor_sync(0xffffffffu, mx, o));
        float ssum = 0.0f;
        for (int t = lane; t < NL; t += 32) {
            float e = __expf(lrow[t] - mx);
            lrow[t] = e;
            ssum += e;
        }
        #pragma unroll
        for (int o = 16; o > 0; o >>= 1) ssum += __shfl_xor_sync(0xffffffffu, ssum, o);
        const float inv = 1.0f / ssum;
        float* arow = g_ATT + ((size_t)(b * NH + h) * NL + irow) * NL;
        for (int t = lane; t < NL; t += 32) arow[t] = lrow[t] * inv;
    }
}

// ---------------- 4) O = attn @ V (64i x 32d tiles, BK=64) -----------------
__global__ void __launch_bounds__(256) gemm_pv_kernel() {
    __shared__ float As[64][68];
    __shared__ float Bs[64][36];
    const int tid = threadIdx.x;
    const int tx = tid & 7, ty = tid >> 3;     // ty 0..31 -> 2 i rows each
    const int it = blockIdx.x, bh = blockIdx.y;
    const int b = bh / NH, h = bh - b * NH;
    const int i0 = it * 64;
    float acc[2][4] = {};

    for (int k0 = 0; k0 < NL; k0 += 64) {
        #pragma unroll
        for (int t = 0; t < 4; t++) {
            int id = tid + t * 256;
            int r = id >> 4, c4 = (id & 15) * 4;
            *(float4*)&As[r][c4] =
                *(const float4*)&g_ATT[((size_t)bh * NL + i0 + r) * NL + k0 + c4];
        }
        #pragma unroll
        for (int t = 0; t < 2; t++) {
            int id = tid + t * 256;
            int r = id >> 3, c4 = (id & 7) * 4;
            *(float4*)&Bs[r][c4] = *(const float4*)&g_V[((size_t)bh * NL + k0 + r) * ND + c4];
        }
        __syncthreads();
        #pragma unroll
        for (int k = 0; k < 64; k++) {
            float a0 = As[ty * 2 + 0][k], a1 = As[ty * 2 + 1][k];
            float4 v4 = *(float4*)&Bs[k][tx * 4];
            acc[0][0] += a0 * v4.x; acc[0][1] += a0 * v4.y; acc[0][2] += a0 * v4.z; acc[0][3] += a0 * v4.w;
            acc[1][0] += a1 * v4.x; acc[1][1] += a1 * v4.y; acc[1][2] += a1 * v4.z; acc[1][3] += a1 * v4.w;
        }
        __syncthreads();
    }
    #pragma unroll
    for (int i = 0; i < 2; i++) {
        int ii = i0 + ty * 2 + i;
        *(float4*)&g_O[(b * NL + ii) * NCS + h * ND + tx * 4] =
            make_float4(acc[i][0], acc[i][1], acc[i][2], acc[i][3]);
    }
}

// ---------------- 5) out = (O @ Wo^T + bo) * mask --------------------------
__global__ void __launch_bounds__(256) gemm_out_kernel(const float* __restrict__ W,
                                                       const float* __restrict__ bias,
                                                       const unsigned char* __restrict__ mask,
                                                       float* __restrict__ out) {
    __shared__ float As[64][36];
    __shared__ float Bs[32][68];
    const int tid = threadIdx.x;
    const int tx = tid & 15, ty = tid >> 4;
    const int m0 = blockIdx.y * 64, n0 = blockIdx.x * 64;
    float acc[4][4] = {};

    for (int k0 = 0; k0 < NCS; k0 += 32) {
        #pragma unroll
        for (int t = 0; t < 2; t++) {
            int id = tid * 2 + t;
            int r = id >> 3, c4 = (id & 7) * 4;
            *(float4*)&As[r][c4] = *(const float4*)&g_O[(m0 + r) * NCS + k0 + c4];
            float4 vb = *(const float4*)&W[(n0 + r) * NCS + k0 + c4];
            Bs[c4 + 0][r] = vb.x; Bs[c4 + 1][r] = vb.y;
            Bs[c4 + 2][r] = vb.z; Bs[c4 + 3][r] = vb.w;
        }
        __syncthreads();
        #pragma unroll
        for (int k = 0; k < 32; k++) {
            float a0 = As[ty * 4 + 0][k], a1 = As[ty * 4 + 1][k];
            float a2 = As[ty * 4 + 2][k], a3 = As[ty * 4 + 3][k];
            float4 b = *(float4*)&Bs[k][tx * 4];
            acc[0][0] += a0 * b.x; acc[0][1] += a0 * b.y; acc[0][2] += a0 * b.z; acc[0][3] += a0 * b.w;
            acc[1][0] += a1 * b.x; acc[1][1] += a1 * b.y; acc[1][2] += a1 * b.z; acc[1][3] += a1 * b.w;
            acc[2][0] += a2 * b.x; acc[2][1] += a2 * b.y; acc[2][2] += a2 * b.z; acc[2][3] += a2 * b.w;
            acc[3][0] += a3 * b.x; acc[3][1] += a3 * b.y; acc[3][2] += a3 * b.z; acc[3][3] += a3 * b.w;
        }
        __syncthreads();
    }
    #pragma unroll
    for (int i = 0; i < 4; i++) {
        int m = m0 + ty * 4 + i;
        float mk = mask_at(mask, m) ? 1.0f : 0.0f;
        #pragma unroll
        for (int j = 0; j < 4; j++) {
            int n = n0 + tx * 4 + j;
            out[m * NCS + n] = (acc[i][j] + bias[n]) * mk;
        }
    }
}

// ---------------- launcher -------------------------------------------------
extern "C" void kernel_launch(void* const* d_in, const int* in_sizes, int n_in,
                              void* d_out, int out_size) {
    const float* s      = (const float*)d_in[0];
    const float* z      = (const float*)d_in[1];
    const unsigned char* mask = (const unsigned char*)d_in[2];
    const float* Wq     = (const float*)d_in[3];
    const float* bq     = (const float*)d_in[4];
    const float* Wk     = (const float*)d_in[5];
    const float* bk     = (const float*)d_in[6];
    const float* Wv     = (const float*)d_in[7];
    const float* bv     = (const float*)d_in[8];
    const float* Wo     = (const float*)d_in[9];
    const float* bo     = (const float*)d_in[10];
    const float* Wp     = (const float*)d_in[11];
    const float* gamma  = (const float*)d_in[12];
    const float* beta   = (const float*)d_in[13];
    float* out          = (float*)d_out;
    (void)in_sizes; (void)n_in; (void)out_size;

    cudaFuncSetAttribute(bias_softmax_kernel,
                         cudaFuncAttributeMaxDynamicSharedMemorySize, BS_SMEM);

    ln_kernel<<<NB * NL, NCS>>>(s, gamma, beta);

    gemm_qkv_kernel<<<dim3(NCS / 64, (NB * NL) / 64, 3), 256>>>(Wq, bq, Wk, bk, Wv, bv);

    gemm_qk_kernel<<<dim3(NL / 64, NL / 64, NB * NH), 256>>>();

    bias_softmax_kernel<<<NB * NL, 512, BS_SMEM>>>(z, Wp, mask);

    gemm_pv_kernel<<<dim3(NL / 64, NB * NH), 256>>>();

    gemm_out_kernel<<<dim3(NCS / 64, (NB * NL) / 64), 256>>>(Wo, bo, mask, out);
}